// round 9
// baseline (speedup 1.0000x reference)
#include <cuda_runtime.h>
#include <stdint.h>

// Depthwise 3x3 conv (256 ch x 2 filters) fused with butterfly wing-swap add.
//   out[c]  = conv(x[c],  w[2c])   + conv(x[cp], w[2cp+1])
//   out[cp] = conv(x[cp], w[2cp])  + conv(x[c],  w[2c+1]),  cp = c+4 within butterfly
// No data smem: thread owns 2 cols x 7 rows of a channel pair, streams 9 input
// rows; horizontal halos via __shfl of neighbor lanes (28 lanes = full 56-col row,
// so shfl-segment edges are the zero-padded plane edges). 3 rolling packed
// accumulator rows (fma.rn.f32x2, (out_c-terms)/(out_cp-terms)), unrolled.
// Block = 256 thr = 8 warps = 8 row-groups = one full (n, pair) plane.

#define CH 256
#define HW 56
#define PLANE (HW * HW)
#define NTHREADS 256
#define NBLOCKS 4096      // 32 batch x 128 pairs, one plane per block

typedef unsigned long long ull;

__device__ __forceinline__ ull fma2(ull a, ull b, ull c) {
    ull d; asm("fma.rn.f32x2 %0, %1, %2, %3;" : "=l"(d) : "l"(a), "l"(b), "l"(c)); return d;
}
__device__ __forceinline__ ull pack2(float lo, float hi) {
    ull r; asm("mov.b64 %0, {%1, %2};" : "=l"(r) : "f"(lo), "f"(hi)); return r;
}
__device__ __forceinline__ float2 unpack2(ull v) {
    float2 r; asm("mov.b64 {%0, %1}, %2;" : "=f"(r.x), "=f"(r.y) : "l"(v)); return r;
}

__global__ __launch_bounds__(NTHREADS, 4)
void conv_butterfly_kernel(const float* __restrict__ x,
                           const float* __restrict__ w,
                           float* __restrict__ out)
{
    // wsm[t*6+0..2] = Wc[t][k] = (w2c[tk],  w2cp1[tk])  -> accum A (out_c terms)
    // wsm[t*6+3..5] = Wp[t][k] = (w2c1[tk], w2cp[tk])   -> accum Q (out_cp terms)
    __shared__ __align__(16) ull wsm[18];

    const int tid  = threadIdx.x;
    const int rg   = tid >> 5;               // row-group 0..7 (7 output rows each)
    const int s    = tid & 31;               // 2-col strip 0..27 (28..31 idle)
    const int bid  = blockIdx.x;
    const int n    = bid >> 7;
    const int pair = bid & 127;
    const int c    = ((pair >> 2) << 3) + (pair & 3);

    if (tid < 18) {
        const float* wa = w + 18 * c;         // [w2c | w2c+1]
        const float* wb = w + 18 * (c + 4);   // [w2cp | w2cp+1]
        const int t = tid / 6, sl = tid - t * 6;
        const int k = t * 3 + (sl < 3 ? sl : sl - 3);
        wsm[tid] = (sl < 3) ? pack2(__ldg(wa + k),     __ldg(wb + 9 + k))
                            : pack2(__ldg(wa + 9 + k), __ldg(wb + k));
    }
    __syncthreads();

    const bool act = (s < 28);
    const int rbase = rg * 7;                 // first output row of this group

    const float2* pc = (const float2*)(x + ((size_t)n * CH + c) * PLANE) + s;
    const float2* pp = (const float2*)(x + ((size_t)n * CH + c + 4) * PLANE) + s;
    float* oc = out + ((size_t)n * CH + c) * PLANE + (size_t)rbase * HW + (s << 1);
    float* op = oc + 4 * PLANE;

    ull A[3][4];     // rolling: [slot][a0,a1,q0,q1]; slot = output_local_row % 3

#define APPLY(SL, T, FRESH) { \
    const ulonglong2 u0 = *(const ulonglong2*)(wsm + (T)*6 + 0); \
    const ulonglong2 u1 = *(const ulonglong2*)(wsm + (T)*6 + 2); \
    const ulonglong2 u2 = *(const ulonglong2*)(wsm + (T)*6 + 4); \
    ull a0 = (FRESH) ? 0ull : A[SL][0], a1 = (FRESH) ? 0ull : A[SL][1]; \
    ull q0 = (FRESH) ? 0ull : A[SL][2], q1 = (FRESH) ? 0ull : A[SL][3]; \
    a0 = fma2(v0, u0.x, a0); a0 = fma2(v1, u0.y, a0); a0 = fma2(v2, u1.x, a0); \
    a1 = fma2(v1, u0.x, a1); a1 = fma2(v2, u0.y, a1); a1 = fma2(v3, u1.x, a1); \
    q0 = fma2(v0, u1.y, q0); q0 = fma2(v1, u2.x, q0); q0 = fma2(v2, u2.y, q0); \
    q1 = fma2(v1, u1.y, q1); q1 = fma2(v2, u2.x, q1); q1 = fma2(v3, u2.y, q1); \
    A[SL][0] = a0; A[SL][1] = a1; A[SL][2] = q0; A[SL][3] = q1; }

    // software pipeline: xn holds input row (rbase-1+rl+1) raw values
    float2 xcn, xpn;
    {
        const int rin = rbase - 1;
        const bool ok = act && (rin >= 0);
        xcn = ok ? __ldg(pc + rin * (HW / 2)) : make_float2(0.f, 0.f);
        xpn = ok ? __ldg(pp + rin * (HW / 2)) : make_float2(0.f, 0.f);
    }

    #pragma unroll
    for (int rl = -1; rl <= 7; ++rl) {        // input row rbase + rl
        const float2 xc = xcn, xp = xpn;
        if (rl < 7) {
            const int rin = rbase + rl + 1;
            const bool ok = act && (rin < HW);
            xcn = ok ? __ldg(pc + rin * (HW / 2)) : make_float2(0.f, 0.f);
            xpn = ok ? __ldg(pp + rin * (HW / 2)) : make_float2(0.f, 0.f);
        }

        // horizontal halos via shuffle (28 lanes span the full row; edges -> 0)
        float xl_c = __shfl_up_sync(0xffffffffu, xc.y, 1);
        float xl_p = __shfl_up_sync(0xffffffffu, xp.y, 1);
        float xr_c = __shfl_down_sync(0xffffffffu, xc.x, 1);
        float xr_p = __shfl_down_sync(0xffffffffu, xp.x, 1);
        if (s == 0)  { xl_c = 0.f; xl_p = 0.f; }
        if (s >= 27) { xr_c = 0.f; xr_p = 0.f; }

        const ull v0 = pack2(xl_c, xl_p);
        const ull v1 = pack2(xc.x, xp.x);
        const ull v2 = pack2(xc.y, xp.y);
        const ull v3 = pack2(xr_c, xr_p);

        // output rows touched by this input row (local): rl+1 (w-row0, fresh),
        // rl (w-row1), rl-1 (w-row2, completes -> store)
        if (rl + 1 <= 6)            APPLY((rl + 1) % 3, 0, true);
        if (rl >= 0 && rl <= 6)     APPLY( rl      % 3, 1, false);
        if (rl - 1 >= 0) {
            APPLY((rl - 1) % 3, 2, false);
            const int sl = (rl - 1) % 3;
            const float2 ua0 = unpack2(A[sl][0]), ua1 = unpack2(A[sl][1]);
            const float2 uq0 = unpack2(A[sl][2]), uq1 = unpack2(A[sl][3]);
            if (act) {
                *(float2*)(oc + (rl - 1) * HW) = make_float2(ua0.x + ua0.y, ua1.x + ua1.y);
                *(float2*)(op + (rl - 1) * HW) = make_float2(uq0.x + uq0.y, uq1.x + uq1.y);
            }
        }
    }
#undef APPLY
}

extern "C" void kernel_launch(void* const* d_in, const int* in_sizes, int n_in,
                              void* d_out, int out_size)
{
    const float* x = (const float*)d_in[0];
    const float* w = (const float*)d_in[1];
    float* out = (float*)d_out;
    (void)in_sizes; (void)n_in; (void)out_size;

    conv_butterfly_kernel<<<NBLOCKS, NTHREADS>>>(x, w, out);
}

// round 10
// speedup vs baseline: 3.0046x; 3.0046x over previous
#include <cuda_runtime.h>
#include <stdint.h>

// Depthwise 3x3 conv (256 ch x 2 filters) fused with butterfly wing-swap add.
//   out[c]  = conv(x[c],  w[2c])   + conv(x[cp], w[2cp+1])
//   out[cp] = conv(x[cp], w[2cp])  + conv(x[c],  w[2c+1]),  cp = c+4 within butterfly
// Persistent blocks, half-plane (28-row) tiles, double-buffered cp.async pipeline.
// R10: non-interleaved smem planes + SCALAR LDS (strip pitch 4 floats x 8 strips
// = exactly 128B per warp-row => provably conflict-free) + register pack2 into
// fma.rn.f32x2. Halves compute-LDS wavefronts vs the (conflicted) LDS.64 scheme.

#define CH 256
#define HW 56
#define PLANE (HW * HW)
#define ST 61                  // floats per smem row (odd -> cross-row conflict-free)
#define TROWS 30               // 28 data rows + 2 halo slots
#define SPLANE (TROWS * ST)    // 1830 floats per channel plane
#define APRON 16               // zeroed floats before first plane (col -1 of slot 0)
#define NTHREADS 224
#define NTILES 8192            // 32 batch * 128 pairs * 2 halves
#define GRID 608               // 4 blocks/SM * 152 SMs

typedef unsigned long long ull;

__device__ __forceinline__ ull fma2(ull a, ull b, ull c) {
    ull d; asm("fma.rn.f32x2 %0, %1, %2, %3;" : "=l"(d) : "l"(a), "l"(b), "l"(c)); return d;
}
__device__ __forceinline__ ull pack2(float lo, float hi) {
    ull r; asm("mov.b64 %0, {%1, %2};" : "=l"(r) : "f"(lo), "f"(hi)); return r;
}
__device__ __forceinline__ float2 unpack2(ull v) {
    float2 r; asm("mov.b64 {%0, %1}, %2;" : "=f"(r.x), "=f"(r.y) : "l"(v)); return r;
}

__global__ __launch_bounds__(NTHREADS, 4)
void conv_butterfly_kernel(const float* __restrict__ x,
                           const float* __restrict__ w,
                           float* __restrict__ out)
{
    extern __shared__ float sm[];                // [APRON][buf0: ch0,ch1][buf1: ch0,ch1]
    __shared__ __align__(16) ull wsm[18];        // per-dr: Wc0,Wc1,Wc2,Wp0,Wp1,Wp2

    const int tid    = threadIdx.x;
    const int warpid = tid >> 5;                 // 0..6
    const int lane   = tid & 31;
    const int lr     = lane & 3;
    const int lc     = lane >> 2;
    const uint32_t smem0 = (uint32_t)__cvta_generic_to_shared(sm);

    // ---- zero apron + pad columns 56..60 of every row of all 4 planes (once)
    for (int i = tid; i < APRON + 4 * TROWS * 5; i += NTHREADS) {
        int off;
        if (i < APRON) off = i;
        else {
            const int j  = i - APRON;
            const int pl = j / (TROWS * 5);          // plane 0..3
            const int r  = (j / 5) % TROWS;
            const int pc = j % 5;
            off = APRON + pl * SPLANE + r * ST + 56 + pc;
        }
        sm[off] = 0.f;
    }

    // ---- prefetch half-tile t into buffer b (3360 4B copies, zfill OOB rows)
    auto prefetch = [&](int t, int b) {
        const int half = t & 1;
        const int p    = (t >> 1) & 127;
        const int n    = t >> 8;
        const int c    = ((p >> 2) << 3) + (p & 3);
        const int h0   = half * 28;
        const float* base = x + ((size_t)n * CH + c) * PLANE;
        #pragma unroll
        for (int k = 0; k < 15; k++) {
            const int i    = tid + k * NTHREADS;         // 0..3359
            const int slot = i / 112;                    // 0..29
            const int rem  = i - slot * 112;
            const int ch   = rem / 56;                   // 0..1
            const int col  = rem - ch * 56;              // 0..55 (consecutive lanes)
            const int h    = h0 - 1 + slot;              // -1..56
            const int sz   = (h >= 0 && h < HW) ? 4 : 0;
            const int hc   = min(max(h, 0), HW - 1);
            const float* src = base + ch * (4 * PLANE) + hc * HW + col;
            const uint32_t dst = smem0 + (uint32_t)((APRON + (2 * b + ch) * SPLANE
                                                     + slot * ST + col) << 2);
            asm volatile("cp.async.ca.shared.global [%0], [%1], 4, %2;"
                         :: "r"(dst), "l"(src), "r"(sz));
        }
    };

    int t = blockIdx.x;
    int b = 0;
    if (t < NTILES) prefetch(t, 0);
    asm volatile("cp.async.commit_group;");

    while (t < NTILES) {
        const int tn = t + GRID;
        if (tn < NTILES) prefetch(tn, b ^ 1);
        asm volatile("cp.async.commit_group;");

        const int half = t & 1;
        const int p    = (t >> 1) & 127;
        const int n    = t >> 8;
        const int c    = ((p >> 2) << 3) + (p & 3);
        const int h0   = half * 28;

        // stage packed weights in shared (18 threads, one ull each)
        if (tid < 18) {
            const float* wa = w + 18 * c;         // [w2c | w2c+1]
            const float* wb = w + 18 * (c + 4);   // [w2cp | w2cp+1]
            const int dr = tid / 6, sl = tid % 6;
            ull v;
            if (sl < 3) { const int k = dr * 3 + sl;     v = pack2(__ldg(wa + k),     __ldg(wb + 9 + k)); }
            else        { const int k = dr * 3 + sl - 3; v = pack2(__ldg(wa + 9 + k), __ldg(wb + k)); }
            wsm[tid] = v;
        }

        asm volatile("cp.async.wait_group 1;");
        __syncthreads();

        const float* p0 = sm + APRON + (2 * b + 0) * SPLANE;   // plane of ch c
        const float* p1 = sm + APRON + (2 * b + 1) * SPLANE;   // plane of ch cp
        float* o0 = out + ((size_t)n * CH + c) * PLANE + h0 * HW;
        float* o1 = o0 + 4 * PLANE;

        const int rl = (warpid << 2) + lr;        // local output row 0..27

        #pragma unroll
        for (int pp = 0; pp < 2; pp++) {
            const int strip = (pp << 3) + lc;     // 0..15, active < 14
            if (strip < 14) {
                const int c0 = strip << 2;
                ull a0 = 0, a1 = 0, a2 = 0, a3 = 0;   // -> out[c]
                ull q0 = 0, q1 = 0, q2 = 0, q3 = 0;   // -> out[cp]
                #pragma unroll
                for (int dr = 0; dr < 3; dr++) {
                    const float* r0 = p0 + (rl + dr) * ST + c0;   // cols c0-1..c0+4
                    const float* r1 = p1 + (rl + dr) * ST + c0;
                    const float e0 = r0[-1], e1 = r0[0], e2 = r0[1],
                                e3 = r0[2],  e4 = r0[3], e5 = r0[4];
                    const float f0 = r1[-1], f1 = r1[0], f2 = r1[1],
                                f3 = r1[2],  f4 = r1[3], f5 = r1[4];
                    const ull v0 = pack2(e0, f0), v1 = pack2(e1, f1), v2 = pack2(e2, f2);
                    const ull v3 = pack2(e3, f3), v4 = pack2(e4, f4), v5 = pack2(e5, f5);

                    const ulonglong2 wA = *(const ulonglong2*)(wsm + dr * 6);
                    const ulonglong2 wB = *(const ulonglong2*)(wsm + dr * 6 + 2);
                    const ulonglong2 wC = *(const ulonglong2*)(wsm + dr * 6 + 4);
                    const ull wc0 = wA.x, wc1 = wA.y, wc2 = wB.x;
                    const ull wp0 = wB.y, wp1 = wC.x, wp2 = wC.y;

                    a0 = fma2(v0, wc0, a0); a0 = fma2(v1, wc1, a0); a0 = fma2(v2, wc2, a0);
                    a1 = fma2(v1, wc0, a1); a1 = fma2(v2, wc1, a1); a1 = fma2(v3, wc2, a1);
                    a2 = fma2(v2, wc0, a2); a2 = fma2(v3, wc1, a2); a2 = fma2(v4, wc2, a2);
                    a3 = fma2(v3, wc0, a3); a3 = fma2(v4, wc1, a3); a3 = fma2(v5, wc2, a3);

                    q0 = fma2(v0, wp0, q0); q0 = fma2(v1, wp1, q0); q0 = fma2(v2, wp2, q0);
                    q1 = fma2(v1, wp0, q1); q1 = fma2(v2, wp1, q1); q1 = fma2(v3, wp2, q1);
                    q2 = fma2(v2, wp0, q2); q2 = fma2(v3, wp1, q2); q2 = fma2(v4, wp2, q2);
                    q3 = fma2(v3, wp0, q3); q3 = fma2(v4, wp1, q3); q3 = fma2(v5, wp2, q3);
                }
                float2 u;
                float4 lo, hi;
                u = unpack2(a0); lo.x = u.x + u.y;
                u = unpack2(a1); lo.y = u.x + u.y;
                u = unpack2(a2); lo.z = u.x + u.y;
                u = unpack2(a3); lo.w = u.x + u.y;
                u = unpack2(q0); hi.x = u.x + u.y;
                u = unpack2(q1); hi.y = u.x + u.y;
                u = unpack2(q2); hi.z = u.x + u.y;
                u = unpack2(q3); hi.w = u.x + u.y;
                *(float4*)(o0 + rl * HW + c0) = lo;
                *(float4*)(o1 + rl * HW + c0) = hi;
            }
        }
        __syncthreads();      // protect buffer b and wsm before refill
        t = tn;
        b ^= 1;
    }
}

extern "C" void kernel_launch(void* const* d_in, const int* in_sizes, int n_in,
                              void* d_out, int out_size)
{
    const float* x = (const float*)d_in[0];
    const float* w = (const float*)d_in[1];
    float* out = (float*)d_out;
    (void)in_sizes; (void)n_in; (void)out_size;

    const int smem_bytes = (APRON + 4 * SPLANE) * (int)sizeof(float);   // 29,344 B
    conv_butterfly_kernel<<<GRID, NTHREADS, smem_bytes>>>(x, w, out);
}